// round 14
// baseline (speedup 1.0000x reference)
#include <cuda_runtime.h>

// LSTM_80582176407707 R13: warp-specialized layer pipelines.
// Warps 0-7  = L1 group: pass1 GEMM (K=1024), L1 sums/act/cells, flagB.
// Warps 8-15 = L0 group: x+h0 GEMM (K=768), L0 sums/act/cells, flagA.
// Groups sync only through global flags -> MUFU bursts of one group overlap
// FFMA of the other on the same SMSPs (walls: FFMA 7.2K, MUFU 5.1K cyc/step).
// B=32, T=2048, I=256, H=512, O=256. 128 CTAs x 512 threads, 1 CTA/SM.

#define BATCH   32
#define TSTEPS  2048
#define INDIM   256
#define HID     512
#define ODIM    256
#define NCTA    128
#define NTH     512
#define RL      264          // red row stride (floats); 264%32==8 -> bank-clean

typedef unsigned long long u64;

// h layout: float[buf][q(128)][b(32)][4] ; h(k) lives in buffer k&1
__device__ float    g_h0[2][16384];
__device__ float    g_h1[2][16384];
__device__ float4   g_xT[(size_t)TSTEPS * 2048];   // [t][q(64)][b(32)] float4
__device__ unsigned g_flagA[NCTA * 32];            // h0 progress
__device__ unsigned g_flagB[NCTA * 32];            // h1 progress

__device__ __forceinline__ u64 fma2(u64 a, u64 b, u64 c) {
    u64 d; asm("fma.rn.f32x2 %0, %1, %2, %3;" : "=l"(d) : "l"(a), "l"(b), "l"(c));
    return d;
}
__device__ __forceinline__ u64 pk(float a, float b) {
    u64 r; asm("mov.b64 %0, {%1, %2};" : "=l"(r) : "f"(a), "f"(b)); return r;
}
__device__ __forceinline__ void upk(u64 v, float& lo, float& hi) {
    asm("mov.b64 {%0, %1}, %2;" : "=f"(lo), "=f"(hi) : "l"(v));
}
__device__ __forceinline__ void fence_gpu() {
    asm volatile("fence.acq_rel.gpu;" ::: "memory");
}
__device__ __forceinline__ void st_flag(unsigned* p, unsigned v) {
    asm volatile("st.relaxed.gpu.u32 [%0], %1;" :: "l"(p), "r"(v) : "memory");
}
__device__ __forceinline__ unsigned ld_flag(unsigned* p) {
    unsigned v; asm volatile("ld.relaxed.gpu.u32 %0, [%1];" : "=r"(v) : "l"(p) : "memory");
    return v;
}
__device__ __forceinline__ float sigf(float x) { return 1.0f / (1.0f + __expf(-x)); }
// tanh via exp (2 MUFU) -- keeps activations off the FMA pipe
__device__ __forceinline__ float tanhfast(float x) {
    float e = __expf(-2.0f * x);
    return (1.0f - e) / (1.0f + e);
}
__device__ __forceinline__ float4 ldca4(const float4* p) {
    float4 v;
    asm volatile("ld.global.ca.v4.f32 {%0, %1, %2, %3}, [%4];"
                 : "=f"(v.x), "=f"(v.y), "=f"(v.z), "=f"(v.w) : "l"(p));
    return v;
}

template <bool CA>
__device__ __forceinline__ void ld_h(const float4* __restrict__ src, int q, int bg,
                                     u64 hlo[4], u64 hhi[4]) {
    #pragma unroll
    for (int j = 0; j < 4; ++j) {
        float4 v = CA ? ldca4(&src[q * 32 + j * 8 + bg])
                      : __ldg (&src[q * 32 + j * 8 + bg]);
        hlo[j] = pk(v.x, v.y); hhi[j] = pk(v.z, v.w);
    }
}

__device__ __forceinline__ void mma_q(u64 acc[16], const float4* __restrict__ Ws,
                                      int qbase, int rg,
                                      const u64 hlo[4], const u64 hhi[4]) {
    #pragma unroll
    for (int i = 0; i < 4; ++i) {
        float4 wv = Ws[qbase + i * 4 + rg];
        u64 wl = pk(wv.x, wv.y), wh = pk(wv.z, wv.w);
        #pragma unroll
        for (int j = 0; j < 4; ++j) {
            acc[i * 4 + j] = fma2(hlo[j], wl, acc[i * 4 + j]);
            acc[i * 4 + j] = fma2(hhi[j], wh, acc[i * 4 + j]);
        }
    }
}

__global__ void transpose_x(const float4* __restrict__ x4) {
    int t = blockIdx.x;
    for (int i = threadIdx.x; i < 2048; i += blockDim.x) {
        int q = i >> 5, b = i & 31;
        g_xT[(size_t)t * 2048 + i] = __ldg(&x4[(size_t)b * (TSTEPS * 64) + t * 64 + q]);
    }
}

#define BAR1() asm volatile("bar.sync 1, 256;" ::: "memory")
#define BAR2() asm volatile("bar.sync 2, 256;" ::: "memory")

#define POLL(ARR, IDX, TGT)                                                    \
    do { while ((int)(ld_flag(&(ARR)[(IDX) * 32]) - (TGT)) < 0)                \
             __nanosleep(28); } while (0)

// store 4x4 tile to red (rows 0-15), col block = kc
#define STORE_RED(RED, KC)                                                     \
    do {                                                                       \
        _Pragma("unroll")                                                      \
        for (int i = 0; i < 4; ++i)                                            \
            _Pragma("unroll")                                                  \
            for (int j = 0; j < 4; ++j) {                                      \
                float lo, hi; upk(acc[i * 4 + j], lo, hi);                     \
                (RED)[(i * 4 + rg) * RL + (KC) * 32 + j * 8 + bg] = lo + hi;   \
            }                                                                  \
    } while (0)

// sums + activation: 256 threads handle 512 (row,b) values, act in-place
#define SUMS_ACT(RED, GAT, BIAS)                                               \
    do {                                                                       \
        _Pragma("unroll")                                                      \
        for (int k2 = 0; k2 < 2; ++k2) {                                       \
            int v = t + 256 * k2, row = v >> 5, b = v & 31;                    \
            float sum = (BIAS)[row];                                           \
            _Pragma("unroll")                                                  \
            for (int k = 0; k < 8; ++k) sum += (RED)[row * RL + k * 32 + b];   \
            (GAT)[row * 32 + b] = ((row >> 2) == 2) ? tanhfast(sum)            \
                                                    : sigf(sum);               \
        }                                                                      \
    } while (0)

__global__ __launch_bounds__(NTH, 1) void lstm_persistent_kernel(
    const float* __restrict__ x,
    const float* __restrict__ Wih0, const float* __restrict__ Whh0,
    const float* __restrict__ bih0, const float* __restrict__ bhh0,
    const float* __restrict__ Wih1, const float* __restrict__ Whh1,
    const float* __restrict__ bih1, const float* __restrict__ bhh1,
    const float* __restrict__ fcw,  const float* __restrict__ fcb,
    float* __restrict__ out)
{
    extern __shared__ float4 smemf4[];
    float4* W0s   = smemf4;                // [192 q][16 l] (x 0-63 | h0 64-191)
    float4* W1s   = W0s + 192 * 16;        // [256 q][16 l] (h0 0-127 | h1 128-255)
    float*  redL1 = (float*)(W1s + 256 * 16);  // [16][RL]
    float*  redL0 = redL1 + 16 * RL;       // [16][RL]
    float*  gat1  = redL0 + 16 * RL;       // [16][32]
    float*  gat0  = gat1 + 512;            // [16][32]
    float*  b1s   = gat0 + 512;            // [16]
    float*  b0s   = b1s + 16;              // [16]

    const int tid  = threadIdx.x;
    const int r    = blockIdx.x;
    const int lane = tid & 31;
    const int rg   = lane >> 3;
    const int bg   = lane & 7;

    unsigned baseA = ld_flag(&g_flagA[r * 32]);
    unsigned baseB = ld_flag(&g_flagB[r * 32]);

    // ---- init: weights ([quad][16 rows]), biases, h1(-1)=0 (buffer 1) ----
    for (int idx = tid; idx < 192 * 16; idx += NTH) {
        int q = idx >> 4, l = idx & 15;
        int grow = ((l >> 2) << 9) + (r << 2) + (l & 3);
        int k0 = q << 2;
        const float* p = (k0 < INDIM) ? (Wih0 + grow * INDIM + k0)
                                      : (Whh0 + grow * HID + (k0 - INDIM));
        W0s[idx] = make_float4(p[0], p[1], p[2], p[3]);
    }
    for (int idx = tid; idx < 256 * 16; idx += NTH) {
        int q = idx >> 4, l = idx & 15;
        int grow = ((l >> 2) << 9) + (r << 2) + (l & 3);
        int k0 = q << 2;
        const float* p = (k0 < HID) ? (Wih1 + grow * HID + k0)
                                    : (Whh1 + grow * HID + (k0 - HID));
        W1s[idx] = make_float4(p[0], p[1], p[2], p[3]);
    }
    if (tid < 16) {
        int grow = ((tid >> 2) << 9) + (r << 2) + (tid & 3);
        b0s[tid] = bih0[grow] + bhh0[grow];
        b1s[tid] = bih1[grow] + bhh1[grow];
    }
    if (tid < 128) g_h1[1][r * 128 + tid] = 0.0f;   // h1(-1) in buffer (-1)&1=1
    __syncthreads();

    u64 hlo[4], hhi[4], acc[16];

    if (tid < 256) {
        // ===================== L1 GROUP (warps 0-7) =====================
        const int kc = tid >> 5;
        const int t  = tid;
        const int cu = (t >> 5) & 3, cb = t & 31;
        float c1 = 0.0f;
        unsigned tA = baseA + 1, tB = baseB;       // targets for s=0

        #pragma unroll 1
        for (int s = 0; s < TSTEPS; ++s) {
            if (t < 128)      { POLL(g_flagA, t, tA);        fence_gpu(); }
            else              { POLL(g_flagB, t - 128, tB);  fence_gpu(); }
            BAR1();

            const float4* h0p = (const float4*)g_h0[s & 1];
            const float4* h1p = (const float4*)g_h1[(s - 1) & 1];
            #pragma unroll
            for (int n = 0; n < 16; ++n) acc[n] = 0ull;
            #pragma unroll 2
            for (int u = 0; u < 16; ++u) {
                int q = kc * 16 + u;
                ld_h<true>(h0p, q, bg, hlo, hhi);
                mma_q(acc, W1s, q * 16, rg, hlo, hhi);
            }
            #pragma unroll 2
            for (int u = 0; u < 16; ++u) {
                int q = kc * 16 + u;
                ld_h<true>(h1p, q, bg, hlo, hhi);
                mma_q(acc, W1s, (128 + q) * 16, rg, hlo, hhi);
            }
            STORE_RED(redL1, kc);
            BAR1();
            SUMS_ACT(redL1, gat1, b1s);
            BAR1();
            if (t < 128) {
                float gi = gat1[cu * 32 + cb];
                float gf = gat1[(4 + cu) * 32 + cb];
                float gg = gat1[(8 + cu) * 32 + cb];
                float go = gat1[(12 + cu) * 32 + cb];
                c1 = gf * c1 + gi * gg;
                g_h1[s & 1][r * 128 + cb * 4 + cu] = go * tanhfast(c1);
            }
            BAR1();
            if (t == 0) { fence_gpu(); st_flag(&g_flagB[r * 32], baseB + s + 1); }
            ++tA; ++tB;
        }
        // ---- FINAL FC (needs all CTAs' h1(2047), buffer 1) ----
        if (t < 128) { POLL(g_flagB, t, baseB + TSTEPS); fence_gpu(); }
        BAR1();
        if (t < 64) {
            int oo = t >> 5, b = t & 31;
            int o = (r << 1) + oo;
            float accf = __ldg(&fcb[o]);
            const float4* h1f = (const float4*)g_h1[1];
            const float4* w4  = (const float4*)(fcw + o * HID);
            #pragma unroll 4
            for (int q = 0; q < 128; ++q) {
                float4 hv = ldca4(&h1f[q * 32 + b]);
                float4 wv = __ldg(&w4[q]);
                accf = fmaf(hv.x, wv.x, accf); accf = fmaf(hv.y, wv.y, accf);
                accf = fmaf(hv.z, wv.z, accf); accf = fmaf(hv.w, wv.w, accf);
            }
            out[b * ODIM + o] = accf;
        }
    } else {
        // ===================== L0 GROUP (warps 8-15) =====================
        const int kc = (tid >> 5) - 8;
        const int t  = tid - 256;
        const int cu = (t >> 5) & 3, cb = t & 31;
        float c0 = 0.0f;

        // ---- prologue: h0(0) from x(0) only ----
        #pragma unroll
        for (int n = 0; n < 16; ++n) acc[n] = 0ull;
        #pragma unroll
        for (int v = 0; v < 8; ++v) {
            int q = kc * 8 + v;
            ld_h<false>(g_xT, q, bg, hlo, hhi);
            mma_q(acc, W0s, q * 16, rg, hlo, hhi);
        }
        STORE_RED(redL0, kc);
        BAR2();
        SUMS_ACT(redL0, gat0, b0s);
        BAR2();
        if (t < 128) {
            float gi = gat0[cu * 32 + cb];
            float gf = gat0[(4 + cu) * 32 + cb];
            float gg = gat0[(8 + cu) * 32 + cb];
            float go = gat0[(12 + cu) * 32 + cb];
            c0 = gf * c0 + gi * gg;
            g_h0[0][r * 128 + cb * 4 + cu] = go * tanhfast(c0);
        }
        BAR2();
        if (t == 0) { fence_gpu(); st_flag(&g_flagA[r * 32], baseA + 1); }

        unsigned tA = baseA + 1, tB = baseB;       // targets for s=0
        #pragma unroll 1
        for (int s = 0; s < TSTEPS - 1; ++s) {
            if (t < 128) { POLL(g_flagA, t, tA); fence_gpu(); }
            BAR2();

            const float4* h0p = (const float4*)g_h0[s & 1];
            const float4* xt  = g_xT + (size_t)(s + 1) * 2048;
            #pragma unroll
            for (int n = 0; n < 16; ++n) acc[n] = 0ull;
            #pragma unroll
            for (int v = 0; v < 8; ++v) {
                int q = kc * 8 + v;
                ld_h<false>(xt, q, bg, hlo, hhi);
                mma_q(acc, W0s, q * 16, rg, hlo, hhi);
            }
            #pragma unroll 2
            for (int u = 0; u < 16; ++u) {
                int q = kc * 16 + u;
                ld_h<true>(h0p, q, bg, hlo, hhi);
                mma_q(acc, W0s, (64 + q) * 16, rg, hlo, hhi);
            }
            STORE_RED(redL0, kc);
            BAR2();
            SUMS_ACT(redL0, gat0, b0s);
            // WAR: h0(s+1) overwrites h0(s-1); readers certify via flagB>=s
            if (t < 128) POLL(g_flagB, t, tB);
            BAR2();
            if (t < 128) {
                float gi = gat0[cu * 32 + cb];
                float gf = gat0[(4 + cu) * 32 + cb];
                float gg = gat0[(8 + cu) * 32 + cb];
                float go = gat0[(12 + cu) * 32 + cb];
                c0 = gf * c0 + gi * gg;
                g_h0[(s + 1) & 1][r * 128 + cb * 4 + cu] = go * tanhfast(c0);
            }
            BAR2();
            if (t == 0) { fence_gpu(); st_flag(&g_flagA[r * 32], baseA + s + 2); }
            ++tA; ++tB;
        }
    }
}

extern "C" void kernel_launch(void* const* d_in, const int* in_sizes, int n_in,
                              void* d_out, int out_size) {
    const float* x    = (const float*)d_in[0];
    const float* Wih0 = (const float*)d_in[1];
    const float* Whh0 = (const float*)d_in[2];
    const float* bih0 = (const float*)d_in[3];
    const float* bhh0 = (const float*)d_in[4];
    const float* Wih1 = (const float*)d_in[5];
    const float* Whh1 = (const float*)d_in[6];
    const float* bih1 = (const float*)d_in[7];
    const float* bhh1 = (const float*)d_in[8];
    const float* fcw  = (const float*)d_in[9];
    const float* fcb  = (const float*)d_in[10];
    float* out = (float*)d_out;

    transpose_x<<<TSTEPS, 256>>>((const float4*)x);

    const int smem_bytes = (192 * 16 + 256 * 16) * 16 +
                           (2 * 16 * RL + 2 * 512 + 32) * 4;   // 152704 B
    cudaFuncSetAttribute(lstm_persistent_kernel,
                         cudaFuncAttributeMaxDynamicSharedMemorySize, smem_bytes);
    lstm_persistent_kernel<<<NCTA, NTH, smem_bytes>>>(
        x, Wih0, Whh0, bih0, bhh0, Wih1, Whh1, bih1, bhh1, fcw, fcb, out);
}

// round 17
// speedup vs baseline: 1.0389x; 1.0389x over previous
#include <cuda_runtime.h>

// LSTM_80582176407707 R16 (R14 resubmit; prior run died to infra):
// R12 base + (a) fused h0 pass: ONE h0 global read feeds both W_hh1 (acc1)
// and W_hh0 (acc0) -> -64 LDG wavefronts/warp/step (L1-wavefront bound);
// (b) activations fused into the 512-thread gate-sum stage; (c) barrier
// filler (x-projection) kept. 128 CTAs x 512 threads, 1 CTA/SM.
// B=32, T=2048, I=256, H=512, O=256.

#define BATCH   32
#define TSTEPS  2048
#define INDIM   256
#define HID     512
#define ODIM    256
#define NCTA    128
#define NTH     512
#define RSTR    520

typedef unsigned long long u64;

// h layout: float[buf][q(128)][b(32)][4 comp]  == unit (4q+comp) of batch b
__device__ float    g_h0[2][16384];
__device__ float    g_h1[2][16384];
__device__ float4   g_xT[(size_t)TSTEPS * 2048];   // [t][q(64)][b(32)] float4
__device__ unsigned g_flag[NCTA * 32];

__device__ __forceinline__ u64 fma2(u64 a, u64 b, u64 c) {
    u64 d; asm("fma.rn.f32x2 %0, %1, %2, %3;" : "=l"(d) : "l"(a), "l"(b), "l"(c));
    return d;
}
__device__ __forceinline__ u64 pk(float a, float b) {
    u64 r; asm("mov.b64 %0, {%1, %2};" : "=l"(r) : "f"(a), "f"(b)); return r;
}
__device__ __forceinline__ void upk(u64 v, float& lo, float& hi) {
    asm("mov.b64 {%0, %1}, %2;" : "=f"(lo), "=f"(hi) : "l"(v));
}
__device__ __forceinline__ void fence_gpu() {
    asm volatile("fence.acq_rel.gpu;" ::: "memory");
}
__device__ __forceinline__ void st_flag(unsigned* p, unsigned v) {
    asm volatile("st.relaxed.gpu.u32 [%0], %1;" :: "l"(p), "r"(v) : "memory");
}
__device__ __forceinline__ unsigned ld_flag(unsigned* p) {
    unsigned v; asm volatile("ld.relaxed.gpu.u32 %0, [%1];" : "=r"(v) : "l"(p) : "memory");
    return v;
}
__device__ __forceinline__ float sigf(float x) { return 1.0f / (1.0f + __expf(-x)); }
__device__ __forceinline__ float4 ldca4(const float4* p) {
    float4 v;
    asm volatile("ld.global.ca.v4.f32 {%0, %1, %2, %3}, [%4];"
                 : "=f"(v.x), "=f"(v.y), "=f"(v.z), "=f"(v.w) : "l"(p));
    return v;
}

template <bool CA>
__device__ __forceinline__ void ld_h(const float4* __restrict__ src, int q, int bg,
                                     u64 hlo[4], u64 hhi[4]) {
    #pragma unroll
    for (int j = 0; j < 4; ++j) {
        float4 v = CA ? ldca4(&src[q * 32 + j * 8 + bg])
                      : __ldg (&src[q * 32 + j * 8 + bg]);
        hlo[j] = pk(v.x, v.y); hhi[j] = pk(v.z, v.w);
    }
}

__device__ __forceinline__ void mma_q(u64 acc[16], const float4* __restrict__ Ws,
                                      int qbase, int rg,
                                      const u64 hlo[4], const u64 hhi[4]) {
    #pragma unroll
    for (int i = 0; i < 4; ++i) {
        float4 wv = Ws[qbase + i * 4 + rg];
        u64 wl = pk(wv.x, wv.y), wh = pk(wv.z, wv.w);
        #pragma unroll
        for (int j = 0; j < 4; ++j) {
            acc[i * 4 + j] = fma2(hlo[j], wl, acc[i * 4 + j]);
            acc[i * 4 + j] = fma2(hhi[j], wh, acc[i * 4 + j]);
        }
    }
}

__global__ void transpose_x(const float4* __restrict__ x4) {
    int t = blockIdx.x;
    for (int i = threadIdx.x; i < 2048; i += blockDim.x) {
        int q = i >> 5, b = i & 31;
        g_xT[(size_t)t * 2048 + i] = __ldg(&x4[(size_t)b * (TSTEPS * 64) + t * 64 + q]);
    }
}

#define STORE_ACCN(A, ROWBASE)                                                 \
    do {                                                                       \
        _Pragma("unroll")                                                      \
        for (int i = 0; i < 4; ++i)                                            \
            _Pragma("unroll")                                                  \
            for (int j = 0; j < 4; ++j) {                                      \
                float lo, hi; upk((A)[i * 4 + j], lo, hi);                     \
                red[((ROWBASE) + i * 4 + rg) * RSTR + w * 32 + j * 8 + bg]     \
                    = lo + hi;                                                 \
            }                                                                  \
    } while (0)

#define BARRIER_PUBLISH()                                                      \
    do { if (tid == 0) { fence_gpu(); st_flag(&g_flag[r * 32], tgt + 1); }     \
         ++tgt; } while (0)

#define BARRIER_POLL()                                                         \
    do { if (tid < NCTA) {                                                     \
             while ((int)(ld_flag(&g_flag[tid * 32]) - tgt) < 0)               \
                 __nanosleep(32);                                              \
             fence_gpu();                                                      \
         }                                                                     \
         __syncthreads(); } while (0)

__global__ __launch_bounds__(NTH, 1) void lstm_persistent_kernel(
    const float* __restrict__ x,
    const float* __restrict__ Wih0, const float* __restrict__ Whh0,
    const float* __restrict__ bih0, const float* __restrict__ bhh0,
    const float* __restrict__ Wih1, const float* __restrict__ Whh1,
    const float* __restrict__ bih1, const float* __restrict__ bhh1,
    const float* __restrict__ fcw,  const float* __restrict__ fcb,
    float* __restrict__ out)
{
    extern __shared__ float4 smemf4[];
    float4* W0s   = smemf4;                // [192 q][16 l]  (x 0-63 | h 64-191)
    float4* W1s   = W0s + 192 * 16;        // [256 q][16 l]
    float*  red   = (float*)(W1s + 256 * 16);  // [48 rows][RSTR]
    float*  gates = red + 48 * RSTR;       // [32 rows][32 b] (ACTIVATED values)
    float*  b1s   = gates + 1024;          // [16]
    float*  b0s   = b1s + 16;              // [16]

    const int tid  = threadIdx.x;
    const int r    = blockIdx.x;
    const int w    = tid >> 5;             // k-chunk warp 0..15
    const int lane = tid & 31;
    const int rg   = lane >> 3;            // row group 0..3
    const int bg   = lane & 7;             // batch group 0..7

    unsigned tgt = ld_flag(&g_flag[r * 32]);   // epoch base

    // ---- weights into SMEM, [quad][row] layout ----
    for (int idx = tid; idx < 192 * 16; idx += NTH) {
        int q = idx >> 4, l = idx & 15;
        int grow = ((l >> 2) << 9) + (r << 2) + (l & 3);
        int k0 = q << 2;
        const float* p = (k0 < INDIM) ? (Wih0 + grow * INDIM + k0)
                                      : (Whh0 + grow * HID + (k0 - INDIM));
        W0s[idx] = make_float4(p[0], p[1], p[2], p[3]);
    }
    for (int idx = tid; idx < 256 * 16; idx += NTH) {
        int q = idx >> 4, l = idx & 15;
        int grow = ((l >> 2) << 9) + (r << 2) + (l & 3);
        int k0 = q << 2;
        const float* p = (k0 < HID) ? (Wih1 + grow * HID + k0)
                                    : (Whh1 + grow * HID + (k0 - HID));
        W1s[idx] = make_float4(p[0], p[1], p[2], p[3]);
    }
    if (tid < 16) {
        int grow = ((tid >> 2) << 9) + (r << 2) + (tid & 3);
        b0s[tid] = bih0[grow] + bhh0[grow];
        b1s[tid] = bih1[grow] + bhh1[grow];
    }
    if (tid < 128) g_h1[0][r * 128 + tid] = 0.0f;   // h1(-1) = 0 (own slice)
    __syncthreads();

    float c0 = 0.0f, c1 = 0.0f;            // c1 in tid<128, c0 in tid 128..255
    u64 hlo[4], hhi[4];
    u64 acc1[16], acc0[16];

    // =============== PROLOGUE: layer0(t=0) (h0(-1)=0 -> x part only) ========
    {
        #pragma unroll
        for (int n = 0; n < 16; ++n) acc0[n] = 0ull;
        #pragma unroll
        for (int v = 0; v < 4; ++v) {
            int q = w * 4 + v;
            ld_h<false>(g_xT, q, bg, hlo, hhi);      // t = 0
            mma_q(acc0, W0s, q * 16, rg, hlo, hhi);
        }
        STORE_ACCN(acc0, 16);
        __syncthreads();
        {
            int row = tid >> 5, b = tid & 31;
            float s0 = b0s[row];
            #pragma unroll
            for (int k = 0; k < 16; ++k) s0 += red[(16 + row) * RSTR + k * 32 + b];
            gates[(16 + row) * 32 + b] = ((row >> 2) == 2) ? tanhf(s0) : sigf(s0);
        }
        __syncthreads();
        if (tid >= 128 && tid < 256) {
            int u = (tid >> 5) & 3, b2 = tid & 31;
            float gi = gates[(16 + u) * 32 + b2];
            float gf = gates[(20 + u) * 32 + b2];
            float gg = gates[(24 + u) * 32 + b2];
            float go = gates[(28 + u) * 32 + b2];
            c0 = gf * c0 + gi * gg;
            g_h0[0][r * 128 + b2 * 4 + u] = go * tanhf(c0);
        }
        __syncthreads();
        BARRIER_PUBLISH();
        // hoisted: x(1) projection partials -> red rows 32-47 (barrier filler)
        {
            #pragma unroll
            for (int n = 0; n < 16; ++n) acc0[n] = 0ull;
            const float4* xt = g_xT + 2048;          // t = 1
            #pragma unroll
            for (int v = 0; v < 4; ++v) {
                int q = w * 4 + v;
                ld_h<false>(xt, q, bg, hlo, hhi);
                mma_q(acc0, W0s, q * 16, rg, hlo, hhi);
            }
            STORE_ACCN(acc0, 32);
        }
        BARRIER_POLL();
    }

    // =============== MAIN LOOP: superstep s = layer1(s) + layer0(s+1) =======
    #pragma unroll 1
    for (int s = 0; s < TSTEPS - 1; ++s) {
        const int p = s & 1;
        const float4* h0p = (const float4*)g_h0[p];
        const float4* h1p = (const float4*)g_h1[p];

        #pragma unroll
        for (int n = 0; n < 16; ++n) { acc1[n] = 0ull; acc0[n] = 0ull; }

        // ---- fused h0 pass: one load feeds W1[:,0:512] AND W0 (Whh0) ----
        #pragma unroll 1
        for (int u = 0; u < 8; ++u) {
            int q = w * 8 + u;
            ld_h<true>(h0p, q, bg, hlo, hhi);
            mma_q(acc1, W1s, q * 16, rg, hlo, hhi);
            mma_q(acc0, W0s, (64 + q) * 16, rg, hlo, hhi);
        }
        // ---- h1 pass: W1[:,512:1024] ----
        #pragma unroll 2
        for (int u = 0; u < 8; ++u) {
            int q = w * 8 + u;
            ld_h<true>(h1p, q, bg, hlo, hhi);
            mma_q(acc1, W1s, (128 + q) * 16, rg, hlo, hhi);
        }
        STORE_ACCN(acc1, 0);
        STORE_ACCN(acc0, 16);
        __syncthreads();

        // ---- gate sums + ACTIVATION (512 threads, 2 values each) ----
        {
            int row = tid >> 5, b = tid & 31;
            float s1 = b1s[row], s0 = b0s[row];
            #pragma unroll
            for (int k = 0; k < 16; ++k) {
                s1 += red[row * RSTR + k * 32 + b];
                s0 += red[(16 + row) * RSTR + k * 32 + b]
                    + red[(32 + row) * RSTR + k * 32 + b];
            }
            bool isg = ((row >> 2) == 2);
            gates[row * 32 + b]        = isg ? tanhf(s1) : sigf(s1);
            gates[(16 + row) * 32 + b] = isg ? tanhf(s0) : sigf(s0);
        }
        __syncthreads();

        // ---- cells (activated gates; only tanh(c) remains) ----
        if (tid < 256) {
            int L = tid >> 7, u = (tid >> 5) & 3, b = tid & 31;
            int ro = L * 16;
            float gi = gates[(ro + u) * 32 + b];
            float gf = gates[(ro + 4 + u) * 32 + b];
            float gg = gates[(ro + 8 + u) * 32 + b];
            float go = gates[(ro + 12 + u) * 32 + b];
            if (L == 0) {                  // layer1 -> h1(s)
                c1 = gf * c1 + gi * gg;
                g_h1[1 - p][r * 128 + b * 4 + u] = go * tanhf(c1);
            } else {                       // layer0 -> h0(s+1)
                c0 = gf * c0 + gi * gg;
                g_h0[1 - p][r * 128 + b * 4 + u] = go * tanhf(c0);
            }
        }
        __syncthreads();
        BARRIER_PUBLISH();

        // ---- hoisted x(s+2) projection during barrier wait ----
        if (s < TSTEPS - 2) {
            #pragma unroll
            for (int n = 0; n < 16; ++n) acc0[n] = 0ull;
            const float4* xt = g_xT + (size_t)(s + 2) * 2048;
            #pragma unroll
            for (int v = 0; v < 4; ++v) {
                int q = w * 4 + v;
                ld_h<false>(xt, q, bg, hlo, hhi);
                mma_q(acc0, W0s, q * 16, rg, hlo, hhi);
            }
            STORE_ACCN(acc0, 32);
        }
        BARRIER_POLL();
    }

    // =============== EPILOGUE: layer1(t=2047) ===============
    {
        const int p = (TSTEPS - 1) & 1;    // 1
        const float4* h0p = (const float4*)g_h0[p];
        const float4* h1p = (const float4*)g_h1[p];
        #pragma unroll
        for (int n = 0; n < 16; ++n) acc1[n] = 0ull;
        #pragma unroll 2
        for (int u = 0; u < 8; ++u) {
            int q = w * 8 + u;
            ld_h<true>(h0p, q, bg, hlo, hhi);
            mma_q(acc1, W1s, q * 16, rg, hlo, hhi);
        }
        #pragma unroll 2
        for (int u = 0; u < 8; ++u) {
            int q = w * 8 + u;
            ld_h<true>(h1p, q, bg, hlo, hhi);
            mma_q(acc1, W1s, (128 + q) * 16, rg, hlo, hhi);
        }
        STORE_ACCN(acc1, 0);
        __syncthreads();
        {
            int row = tid >> 5, b = tid & 31;
            float s1 = b1s[row];
            #pragma unroll
            for (int k = 0; k < 16; ++k) s1 += red[row * RSTR + k * 32 + b];
            gates[row * 32 + b] = ((row >> 2) == 2) ? tanhf(s1) : sigf(s1);
        }
        __syncthreads();
        if (tid < 128) {
            int u = (tid >> 5) & 3, b = tid & 31;
            float gi = gates[(u) * 32 + b];
            float gf = gates[(4 + u) * 32 + b];
            float gg = gates[(8 + u) * 32 + b];
            float go = gates[(12 + u) * 32 + b];
            c1 = gf * c1 + gi * gg;
            g_h1[1 - p][r * 128 + b * 4 + u] = go * tanhf(c1);  // -> buffer 0
        }
        __syncthreads();
        BARRIER_PUBLISH();
        BARRIER_POLL();
    }

    // =============== FINAL FC ===============
    if (tid < 64) {
        int oo = tid >> 5, b = tid & 31;
        int o = (r << 1) + oo;
        float accf = __ldg(&fcb[o]);
        const float4* h1f = (const float4*)g_h1[0];
        const float4* w4  = (const float4*)(fcw + o * HID);
        #pragma unroll 4
        for (int q = 0; q < 128; ++q) {
            float4 hv = ldca4(&h1f[q * 32 + b]);
            float4 wv = __ldg(&w4[q]);
            accf = fmaf(hv.x, wv.x, accf); accf = fmaf(hv.y, wv.y, accf);
            accf = fmaf(hv.z, wv.z, accf); accf = fmaf(hv.w, wv.w, accf);
        }
        out[b * ODIM + o] = accf;
    }
}

extern "C" void kernel_launch(void* const* d_in, const int* in_sizes, int n_in,
                              void* d_out, int out_size) {
    const float* x    = (const float*)d_in[0];
    const float* Wih0 = (const float*)d_in[1];
    const float* Whh0 = (const float*)d_in[2];
    const float* bih0 = (const float*)d_in[3];
    const float* bhh0 = (const float*)d_in[4];
    const float* Wih1 = (const float*)d_in[5];
    const float* Whh1 = (const float*)d_in[6];
    const float* bih1 = (const float*)d_in[7];
    const float* bhh1 = (const float*)d_in[8];
    const float* fcw  = (const float*)d_in[9];
    const float* fcb  = (const float*)d_in[10];
    float* out = (float*)d_out;

    transpose_x<<<TSTEPS, 256>>>((const float4*)x);

    const int smem_bytes = (192 * 16 + 256 * 16) * 16 +
                           (48 * RSTR + 1024 + 32) * 4;   // 218752 B
    cudaFuncSetAttribute(lstm_persistent_kernel,
                         cudaFuncAttributeMaxDynamicSharedMemorySize, smem_bytes);
    lstm_persistent_kernel<<<NCTA, NTH, smem_bytes>>>(
        x, Wih0, Whh0, bih0, bhh0, Wih1, Whh1, bih1, bhh1, fcw, fcb, out);
}